// round 5
// baseline (speedup 1.0000x reference)
#include <cuda_runtime.h>
#include <cuda_bf16.h>

#define NB 4
#define NL 2048
#define ND 1024
#define NH 16
#define DH 64

#define QT  16    // query rows per attention CTA
#define SS  2052  // S row stride: %32==4 (bank spread), %4==0 (float4 ok)
#define KT1 512   // phase-1 k-rows per tile (loaded in two 32-dd halves)
#define KSP 36    // phase-1 K tile row stride (32 dd + pad, mult of 4)
#define KT3 256   // phase-3 v-rows per tile
#define VSP 68    // phase-3 V tile row stride (mult of 4)
#define QSP 68    // Q tile row stride
#define BUFF (KT1*KSP)   // 18432 floats: K half-tile / V tile / 16x16x64 reduction
#define SMEM_FLOATS (QT*SS + BUFF + QT*QSP)
#define ATHR 512  // attention CTA threads (16 warps)

// ---- packed f32x2 helpers (SASS FFMA2 — only reachable via PTX) ----
__device__ __forceinline__ unsigned long long pk2(float v) {
    unsigned long long r;
    asm("mov.b64 %0, {%1, %2};" : "=l"(r) : "f"(v), "f"(v));
    return r;
}
__device__ __forceinline__ void fma2(unsigned long long& d,
                                     unsigned long long a, unsigned long long b) {
    asm("fma.rn.f32x2 %0, %1, %2, %0;" : "+l"(d) : "l"(a), "l"(b));
}
__device__ __forceinline__ void unpk(unsigned long long v, float& lo, float& hi) {
    asm("mov.b64 {%0, %1}, %2;" : "=f"(lo), "=f"(hi) : "l"(v));
}

// Scratch (device globals — no allocation allowed in kernel_launch)
__device__ float g_k[(size_t)NB * NH * NL * DH];
__device__ float g_v[(size_t)NB * NH * NL * DH];
__device__ float g_q[(size_t)NB * NH * NL * DH];
__device__ float g_ctx[(size_t)NB * NL * ND];

// ---------------------------------------------------------------------------
// SGEMM: dst = (A[M,1024] @ W[1024,1024] + bias) * scale   (packed FFMA2)
// 128x128 block tile, 8x8 microtile, K-tile 16, double-buffered smem with
// register prefetch.
// ---------------------------------------------------------------------------
__global__ __launch_bounds__(256, 2) void sgemm_bias_kernel(
    const float* __restrict__ A, const float* __restrict__ W,
    const float* __restrict__ bias, float* __restrict__ dst,
    float scale, int scatter)
{
    __shared__ float As[2][16][128];
    __shared__ float Bs[2][16][128];

    const int t  = threadIdx.x;
    const int m0 = blockIdx.y * 128;
    const int n0 = blockIdx.x * 128;
    const int ty = t >> 4, tx = t & 15;

    unsigned long long acc2[4][8];
#pragma unroll
    for (int ip = 0; ip < 4; ip++)
#pragma unroll
        for (int j = 0; j < 8; j++) acc2[ip][j] = 0ull;

    float4 pa[2], pb[2];
#pragma unroll
    for (int i = 0; i < 2; i++) {
        const int idx = t + i * 256;
        pa[i] = *(const float4*)(A + (size_t)(m0 + (idx >> 2)) * ND + ((idx & 3) * 4));
        pb[i] = *(const float4*)(W + (size_t)(idx >> 5) * ND + n0 + (idx & 31) * 4);
    }
#pragma unroll
    for (int i = 0; i < 2; i++) {
        const int idx = t + i * 256;
        const int r = idx >> 2, c = (idx & 3) * 4;
        As[0][c + 0][r] = pa[i].x; As[0][c + 1][r] = pa[i].y;
        As[0][c + 2][r] = pa[i].z; As[0][c + 3][r] = pa[i].w;
        *(float4*)&Bs[0][idx >> 5][(idx & 31) * 4] = pb[i];
    }
    __syncthreads();

    int cur = 0;
    for (int k0 = 0; k0 < ND; k0 += 16) {
        const int has_next = (k0 + 16 < ND);
        if (has_next) {
#pragma unroll
            for (int i = 0; i < 2; i++) {
                const int idx = t + i * 256;
                pa[i] = *(const float4*)(A + (size_t)(m0 + (idx >> 2)) * ND + k0 + 16 + ((idx & 3) * 4));
                pb[i] = *(const float4*)(W + (size_t)(k0 + 16 + (idx >> 5)) * ND + n0 + (idx & 31) * 4);
            }
        }
#pragma unroll
        for (int kk = 0; kk < 16; kk++) {
            const ulonglong2 ap0 = *(const ulonglong2*)&As[cur][kk][ty * 8];
            const ulonglong2 ap1 = *(const ulonglong2*)&As[cur][kk][ty * 8 + 4];
            const float4 b0 = *(const float4*)&Bs[cur][kk][tx * 8];
            const float4 b1 = *(const float4*)&Bs[cur][kk][tx * 8 + 4];
            unsigned long long bd[8];
            bd[0] = pk2(b0.x); bd[1] = pk2(b0.y); bd[2] = pk2(b0.z); bd[3] = pk2(b0.w);
            bd[4] = pk2(b1.x); bd[5] = pk2(b1.y); bd[6] = pk2(b1.z); bd[7] = pk2(b1.w);
#pragma unroll
            for (int j = 0; j < 8; j++) {
                fma2(acc2[0][j], ap0.x, bd[j]);
                fma2(acc2[1][j], ap0.y, bd[j]);
                fma2(acc2[2][j], ap1.x, bd[j]);
                fma2(acc2[3][j], ap1.y, bd[j]);
            }
        }
        if (has_next) {
            const int nxt = cur ^ 1;
#pragma unroll
            for (int i = 0; i < 2; i++) {
                const int idx = t + i * 256;
                const int r = idx >> 2, c = (idx & 3) * 4;
                As[nxt][c + 0][r] = pa[i].x; As[nxt][c + 1][r] = pa[i].y;
                As[nxt][c + 2][r] = pa[i].z; As[nxt][c + 3][r] = pa[i].w;
                *(float4*)&Bs[nxt][idx >> 5][(idx & 31) * 4] = pb[i];
            }
        }
        __syncthreads();
        cur ^= 1;
    }

#pragma unroll
    for (int ip = 0; ip < 4; ip++) {
#pragma unroll
        for (int j = 0; j < 8; j++) {
            float lo, hi;
            unpk(acc2[ip][j], lo, hi);
            const int c = n0 + tx * 8 + j;
            const float bias_c = bias[c];
#pragma unroll
            for (int s = 0; s < 2; s++) {
                const int r = m0 + ty * 8 + ip * 2 + s;
                const float v = ((s ? hi : lo) + bias_c) * scale;
                if (scatter) {
                    const int b = r >> 11, l = r & (NL - 1);
                    const int h = c >> 6,  d = c & 63;
                    dst[((size_t)(b * NH + h) * NL + l) * DH + d] = v;
                } else {
                    dst[(size_t)r * ND + c] = v;
                }
            }
        }
    }
}

// ---------------------------------------------------------------------------
// Attention: per (b, h, 16-query tile). 512 threads (16 warps) for latency
// hiding; small per-thread tiles (acc = 16 ull) to avoid register spills.
// Reduction-dim FFMA2 pairing: acc lanes = (sum even dd, sum odd dd).
// Q reads are full-warp broadcasts (qg constant within a warp) -> cheap LDS.
// ---------------------------------------------------------------------------
__global__ __launch_bounds__(ATHR, 1) void attn_kernel(
    const int* __restrict__ mask, float* __restrict__ attn_out)
{
    extern __shared__ float sm[];
    float* S   = sm;                 // QT * SS
    float* buf = S + QT * SS;        // K half-tile [512][36] / V tile [256][68] / red
    float* Qs  = buf + BUFF;         // QT * QSP

    const int t  = threadIdx.x;
    const int q0 = blockIdx.x * QT;
    const int h  = blockIdx.y;
    const int b  = blockIdx.z;

    const float* qptr = g_q + (size_t)(b * NH + h) * NL * DH;
    const float* kptr = g_k + (size_t)(b * NH + h) * NL * DH;
    const float* vptr = g_v + (size_t)(b * NH + h) * NL * DH;

    // Load Q tile [16][64] (visibility covered by first sync in phase-1 loop)
    for (int idx = t; idx < QT * DH; idx += ATHR) {
        const int q = idx >> 6, d = idx & 63;
        Qs[q * QSP + d] = qptr[(size_t)(q0 + q) * DH + d];
    }

    // ---------------- Phase 1: S = Q @ K^T ----------------
    {
        const int qg = t >> 8;       // 0..1 : 8 q-rows each (warp-uniform)
        const int kg = t & 255;      // 0..255: k-rows kg + 256*j

        for (int kt = 0; kt < NL; kt += KT1) {
            unsigned long long acc[8][2];
#pragma unroll
            for (int i = 0; i < 8; i++) { acc[i][0] = 0ull; acc[i][1] = 0ull; }

#pragma unroll
            for (int half = 0; half < 2; half++) {
                const int dh0 = half * 32;
                __syncthreads();
                // load K half-tile [512 rows][32 dd] -> buf stride KSP
#pragma unroll
                for (int i = 0; i < 8; i++) {
                    const int idx = t + i * ATHR;
                    const int row = idx >> 3, c = (idx & 7) * 4;
                    const float4 v = *(const float4*)(kptr + (size_t)(kt + row) * DH + dh0 + c);
                    *(float4*)(buf + row * KSP + c) = v;
                }
                __syncthreads();

#pragma unroll
                for (int dd4 = 0; dd4 < 32; dd4 += 4) {
                    const ulonglong2 kv0 = *(const ulonglong2*)(buf + (kg      ) * KSP + dd4);
                    const ulonglong2 kv1 = *(const ulonglong2*)(buf + (kg + 256) * KSP + dd4);
#pragma unroll
                    for (int i = 0; i < 8; i++) {
                        const ulonglong2 qv =
                            *(const ulonglong2*)(Qs + (qg * 8 + i) * QSP + dh0 + dd4);
                        fma2(acc[i][0], qv.x, kv0.x);
                        fma2(acc[i][0], qv.y, kv0.y);
                        fma2(acc[i][1], qv.x, kv1.x);
                        fma2(acc[i][1], qv.y, kv1.y);
                    }
                }
            }
#pragma unroll
            for (int i = 0; i < 8; i++) {
#pragma unroll
                for (int j = 0; j < 2; j++) {
                    float lo, hi;
                    unpk(acc[i][j], lo, hi);
                    S[(qg * 8 + i) * SS + kt + kg + 256 * j] = lo + hi;
                }
            }
        }
    }
    __syncthreads();

    // ---------------- Phase 2: masked softmax (1 row per warp, float4) ----------------
    {
        const int w = t >> 5, lane = t & 31;
        const int qq = q0 + w;
        const int4*   mrow4 = (const int4*)(mask + ((size_t)b * NL + qq) * NL);
        float4* srow4 = (float4*)(S + w * SS);

        float mx = -3.0e38f;
        for (int i = lane; i < NL / 4; i += 32) {
            const float4 s = srow4[i];
            const int4   m = mrow4[i];
            mx = fmaxf(mx, m.x ? -1.0e18f : s.x);
            mx = fmaxf(mx, m.y ? -1.0e18f : s.y);
            mx = fmaxf(mx, m.z ? -1.0e18f : s.z);
            mx = fmaxf(mx, m.w ? -1.0e18f : s.w);
        }
#pragma unroll
        for (int o = 16; o > 0; o >>= 1)
            mx = fmaxf(mx, __shfl_xor_sync(0xffffffffu, mx, o));

        float sum = 0.f;
        for (int i = lane; i < NL / 4; i += 32) {
            const float4 s = srow4[i];
            const int4   m = mrow4[i];
            float4 p;
            p.x = m.x ? 0.f : __expf(s.x - mx);
            p.y = m.y ? 0.f : __expf(s.y - mx);
            p.z = m.z ? 0.f : __expf(s.z - mx);
            p.w = m.w ? 0.f : __expf(s.w - mx);
            srow4[i] = p;
            sum += p.x + p.y + p.z + p.w;
        }
#pragma unroll
        for (int o = 16; o > 0; o >>= 1)
            sum += __shfl_xor_sync(0xffffffffu, sum, o);

        const float inv = 1.f / sum;
        if (h == 0) {
            float4* arow4 = (float4*)(attn_out + ((size_t)b * NL + qq) * NL);
            for (int i = lane; i < NL / 4; i += 32) {
                float4 p = srow4[i];
                p.x *= inv; p.y *= inv; p.z *= inv; p.w *= inv;
                srow4[i] = p;
                arow4[i] = p;
            }
        } else {
            for (int i = lane; i < NL / 4; i += 32) {
                float4 p = srow4[i];
                p.x *= inv; p.y *= inv; p.z *= inv; p.w *= inv;
                srow4[i] = p;
            }
        }
    }

    // ---------------- Phase 3: ctx = P @ V (ksplit x16 + reduction) ----------------
    {
        const int ks = t >> 5;        // 0..15 : k-chunk of 16 rows within each tile
        const int qg = (t >> 4) & 1;  // 0..1  : 8 q-rows each
        const int dg = t & 15;        // 0..15 : d columns dg*4 .. dg*4+3

        unsigned long long acc[8][2];
#pragma unroll
        for (int i = 0; i < 8; i++) { acc[i][0] = 0ull; acc[i][1] = 0ull; }

        for (int kt = 0; kt < NL; kt += KT3) {
            __syncthreads();
            // load V tile [256][64] -> buf stride VSP
#pragma unroll
            for (int i = 0; i < 8; i++) {
                const int idx = t + i * ATHR;
                const int row = idx >> 4, c = (idx & 15) * 4;
                const float4 v = *(const float4*)(vptr + (size_t)(kt + row) * DH + c);
                *(float4*)(buf + row * VSP + c) = v;
            }
            __syncthreads();

#pragma unroll
            for (int kk4 = 0; kk4 < 16; kk4 += 4) {
                float4 pv[8];
#pragma unroll
                for (int i = 0; i < 8; i++)
                    pv[i] = *(const float4*)(S + (qg * 8 + i) * SS + kt + ks * 16 + kk4);
#pragma unroll
                for (int kk = 0; kk < 4; kk++) {
                    const ulonglong2 vv =
                        *(const ulonglong2*)(buf + (ks * 16 + kk4 + kk) * VSP + dg * 4);
#pragma unroll
                    for (int i = 0; i < 8; i++) {
                        const float pf = (kk == 0) ? pv[i].x : (kk == 1) ? pv[i].y
                                       : (kk == 2) ? pv[i].z : pv[i].w;
                        const unsigned long long pd = pk2(pf);
                        fma2(acc[i][0], pd, vv.x);
                        fma2(acc[i][1], pd, vv.y);
                    }
                }
            }
        }
        __syncthreads();
        // partial results: red[ks][16 q][64 d] aliased onto buf (16384 floats)
        float* red = buf;
#pragma unroll
        for (int i = 0; i < 8; i++) {
            float* rb = red + ((ks * QT) + qg * 8 + i) * DH + dg * 4;
            *(unsigned long long*)(rb)     = acc[i][0];
            *(unsigned long long*)(rb + 2) = acc[i][1];
        }
        __syncthreads();

        float* ctx = g_ctx + (size_t)(b * NL + q0) * ND + h * DH;
        for (int idx = t; idx < QT * DH; idx += ATHR) {
            const int q = idx >> 6, d = idx & 63;
            float s = 0.f;
#pragma unroll
            for (int g = 0; g < 16; g++) s += red[(g * QT + q) * DH + d];
            ctx[(size_t)q * ND + d] = s;
        }
    }
}

// ---------------------------------------------------------------------------
extern "C" void kernel_launch(void* const* d_in, const int* in_sizes, int n_in,
                              void* d_out, int out_size)
{
    const float* key   = (const float*)d_in[0];
    const float* value = (const float*)d_in[1];
    const float* query = (const float*)d_in[2];
    const int*   mask  = (const int*)d_in[3];
    const float* Wk = (const float*)d_in[4];
    const float* bk = (const float*)d_in[5];
    const float* Wv = (const float*)d_in[6];
    const float* bv = (const float*)d_in[7];
    const float* Wq = (const float*)d_in[8];
    const float* bq = (const float*)d_in[9];
    const float* Wo = (const float*)d_in[10];
    const float* bo = (const float*)d_in[11];

    float* out      = (float*)d_out;
    float* attn_out = out + (size_t)NB * NL * ND;

    float *gk, *gv, *gq, *gctx;
    cudaGetSymbolAddress((void**)&gk,   g_k);
    cudaGetSymbolAddress((void**)&gv,   g_v);
    cudaGetSymbolAddress((void**)&gq,   g_q);
    cudaGetSymbolAddress((void**)&gctx, g_ctx);

    static int attr_set = 0;
    if (!attr_set) {
        cudaFuncSetAttribute(attn_kernel,
                             cudaFuncAttributeMaxDynamicSharedMemorySize,
                             SMEM_FLOATS * (int)sizeof(float));
        attr_set = 1;
    }

    const dim3 gemm_grid(ND / 128, (NB * NL) / 128);  // 8 x 64
    sgemm_bias_kernel<<<gemm_grid, 256>>>(key,   Wk, bk, gk, 1.0f,   1);
    sgemm_bias_kernel<<<gemm_grid, 256>>>(value, Wv, bv, gv, 1.0f,   1);
    sgemm_bias_kernel<<<gemm_grid, 256>>>(query, Wq, bq, gq, 0.125f, 1);

    const dim3 attn_grid(NL / QT, NH, NB);            // 128 x 16 x 4
    attn_kernel<<<attn_grid, ATHR, SMEM_FLOATS * (int)sizeof(float)>>>(mask, attn_out);

    sgemm_bias_kernel<<<gemm_grid, 256>>>(gctx, Wo, bo, out, 1.0f, 0);
}

// round 6
// speedup vs baseline: 1.0702x; 1.0702x over previous
#include <cuda_runtime.h>
#include <cuda_bf16.h>

#define NB 4
#define NL 2048
#define ND 1024
#define NH 16
#define DH 64

#define QT  16    // query rows per attention CTA
#define SS  2052  // S row stride: %32==4 (bank spread), %4==0 (float4 ok)
#define KC  256   // phase-1 k-rows per chunk (32 dd wide)
#define KSP 36    // phase-1 chunk row stride
#define VC  128   // phase-3 v-rows per chunk (64 dd wide)
#define VSP 68    // phase-3 chunk row stride
#define QSP 68    // Q tile row stride
#define BUFW (KC*KSP)    // 9216 floats per ping-pong buffer (>= VC*VSP = 8704)
#define SMEM_FLOATS (QT*SS + 2*BUFW + QT*QSP + 16)

// ---- packed f32x2 helpers (SASS FFMA2 — only reachable via PTX) ----
__device__ __forceinline__ unsigned long long pk2(float v) {
    unsigned long long r;
    asm("mov.b64 %0, {%1, %2};" : "=l"(r) : "f"(v), "f"(v));
    return r;
}
__device__ __forceinline__ void fma2(unsigned long long& d,
                                     unsigned long long a, unsigned long long b) {
    asm("fma.rn.f32x2 %0, %1, %2, %0;" : "+l"(d) : "l"(a), "l"(b));
}
__device__ __forceinline__ void unpk(unsigned long long v, float& lo, float& hi) {
    asm("mov.b64 {%0, %1}, %2;" : "=f"(lo), "=f"(hi) : "l"(v));
}
// ---- cp.async helpers ----
__device__ __forceinline__ void cpasync16(unsigned dst, const float* src) {
    asm volatile("cp.async.cg.shared.global [%0], [%1], 16;" :: "r"(dst), "l"(src) : "memory");
}
__device__ __forceinline__ void cp_commit() {
    asm volatile("cp.async.commit_group;" ::: "memory");
}
__device__ __forceinline__ void cp_wait0() {
    asm volatile("cp.async.wait_group 0;" ::: "memory");
}
__device__ __forceinline__ void cp_wait1() {
    asm volatile("cp.async.wait_group 1;" ::: "memory");
}

// Scratch (device globals — no allocation allowed in kernel_launch)
__device__ float g_k[(size_t)NB * NH * NL * DH];
__device__ float g_v[(size_t)NB * NH * NL * DH];
__device__ float g_q[(size_t)NB * NH * NL * DH];
__device__ float g_ctx[(size_t)NB * NL * ND];

// ---------------------------------------------------------------------------
// SGEMM: dst = (A[M,1024] @ W[1024,1024] + bias) * scale   (packed FFMA2)
// 128x128 block tile, 8x8 microtile, K-tile 16, double-buffered smem with
// register prefetch. (unchanged from round 4 — known good)
// ---------------------------------------------------------------------------
__global__ __launch_bounds__(256, 2) void sgemm_bias_kernel(
    const float* __restrict__ A, const float* __restrict__ W,
    const float* __restrict__ bias, float* __restrict__ dst,
    float scale, int scatter)
{
    __shared__ float As[2][16][128];
    __shared__ float Bs[2][16][128];

    const int t  = threadIdx.x;
    const int m0 = blockIdx.y * 128;
    const int n0 = blockIdx.x * 128;
    const int ty = t >> 4, tx = t & 15;

    unsigned long long acc2[4][8];
#pragma unroll
    for (int ip = 0; ip < 4; ip++)
#pragma unroll
        for (int j = 0; j < 8; j++) acc2[ip][j] = 0ull;

    float4 pa[2], pb[2];
#pragma unroll
    for (int i = 0; i < 2; i++) {
        const int idx = t + i * 256;
        pa[i] = *(const float4*)(A + (size_t)(m0 + (idx >> 2)) * ND + ((idx & 3) * 4));
        pb[i] = *(const float4*)(W + (size_t)(idx >> 5) * ND + n0 + (idx & 31) * 4);
    }
#pragma unroll
    for (int i = 0; i < 2; i++) {
        const int idx = t + i * 256;
        const int r = idx >> 2, c = (idx & 3) * 4;
        As[0][c + 0][r] = pa[i].x; As[0][c + 1][r] = pa[i].y;
        As[0][c + 2][r] = pa[i].z; As[0][c + 3][r] = pa[i].w;
        *(float4*)&Bs[0][idx >> 5][(idx & 31) * 4] = pb[i];
    }
    __syncthreads();

    int cur = 0;
    for (int k0 = 0; k0 < ND; k0 += 16) {
        const int has_next = (k0 + 16 < ND);
        if (has_next) {
#pragma unroll
            for (int i = 0; i < 2; i++) {
                const int idx = t + i * 256;
                pa[i] = *(const float4*)(A + (size_t)(m0 + (idx >> 2)) * ND + k0 + 16 + ((idx & 3) * 4));
                pb[i] = *(const float4*)(W + (size_t)(k0 + 16 + (idx >> 5)) * ND + n0 + (idx & 31) * 4);
            }
        }
#pragma unroll
        for (int kk = 0; kk < 16; kk++) {
            const ulonglong2 ap0 = *(const ulonglong2*)&As[cur][kk][ty * 8];
            const ulonglong2 ap1 = *(const ulonglong2*)&As[cur][kk][ty * 8 + 4];
            const float4 b0 = *(const float4*)&Bs[cur][kk][tx * 8];
            const float4 b1 = *(const float4*)&Bs[cur][kk][tx * 8 + 4];
            unsigned long long bd[8];
            bd[0] = pk2(b0.x); bd[1] = pk2(b0.y); bd[2] = pk2(b0.z); bd[3] = pk2(b0.w);
            bd[4] = pk2(b1.x); bd[5] = pk2(b1.y); bd[6] = pk2(b1.z); bd[7] = pk2(b1.w);
#pragma unroll
            for (int j = 0; j < 8; j++) {
                fma2(acc2[0][j], ap0.x, bd[j]);
                fma2(acc2[1][j], ap0.y, bd[j]);
                fma2(acc2[2][j], ap1.x, bd[j]);
                fma2(acc2[3][j], ap1.y, bd[j]);
            }
        }
        if (has_next) {
            const int nxt = cur ^ 1;
#pragma unroll
            for (int i = 0; i < 2; i++) {
                const int idx = t + i * 256;
                const int r = idx >> 2, c = (idx & 3) * 4;
                As[nxt][c + 0][r] = pa[i].x; As[nxt][c + 1][r] = pa[i].y;
                As[nxt][c + 2][r] = pa[i].z; As[nxt][c + 3][r] = pa[i].w;
                *(float4*)&Bs[nxt][idx >> 5][(idx & 31) * 4] = pb[i];
            }
        }
        __syncthreads();
        cur ^= 1;
    }

#pragma unroll
    for (int ip = 0; ip < 4; ip++) {
#pragma unroll
        for (int j = 0; j < 8; j++) {
            float lo, hi;
            unpk(acc2[ip][j], lo, hi);
            const int c = n0 + tx * 8 + j;
            const float bias_c = bias[c];
#pragma unroll
            for (int s = 0; s < 2; s++) {
                const int r = m0 + ty * 8 + ip * 2 + s;
                const float v = ((s ? hi : lo) + bias_c) * scale;
                if (scatter) {
                    const int b = r >> 11, l = r & (NL - 1);
                    const int h = c >> 6,  d = c & 63;
                    dst[((size_t)(b * NH + h) * NL + l) * DH + d] = v;
                } else {
                    dst[(size_t)r * ND + c] = v;
                }
            }
        }
    }
}

// ---------------------------------------------------------------------------
// Attention: per (b, h, 16-query tile), 256 threads.
// cp.async 2-stage pipelined K/V chunk streaming overlapped with FFMA2 math.
// Phase 1: S = Q@K^T, 16 chunks of 256 rows x 32 dd; thread tile 8q x 2k.
// Phase 2: single-pass masked exp + row sums (no max pass; normalization
//          deferred to phase-3 epilogue via invs[]); h==0 writes attn_out.
// Phase 3: ctx = P@V, 16 chunks of 128 rows x 64 dd, ksplit x8 + reduction.
// ---------------------------------------------------------------------------
__global__ __launch_bounds__(256, 1) void attn_kernel(
    const int* __restrict__ mask, float* __restrict__ attn_out)
{
    extern __shared__ float sm[];
    float* S    = sm;                    // QT * SS
    float* bufp[2];
    bufp[0] = S + QT * SS;               // BUFW
    bufp[1] = bufp[0] + BUFW;            // BUFW
    float* Qs   = bufp[1] + BUFW;        // QT * QSP
    float* invs = Qs + QT * QSP;         // 16

    unsigned bufa[2];
    bufa[0] = (unsigned)__cvta_generic_to_shared(bufp[0]);
    bufa[1] = (unsigned)__cvta_generic_to_shared(bufp[1]);

    const int t  = threadIdx.x;
    const int q0 = blockIdx.x * QT;
    const int h  = blockIdx.y;
    const int b  = blockIdx.z;

    const float* qptr = g_q + (size_t)(b * NH + h) * NL * DH;
    const float* kptr = g_k + (size_t)(b * NH + h) * NL * DH;
    const float* vptr = g_v + (size_t)(b * NH + h) * NL * DH;

    // Load Q tile [16][64] (visible after first pipeline sync)
    for (int idx = t; idx < QT * DH; idx += 256) {
        const int q = idx >> 6, d = idx & 63;
        Qs[q * QSP + d] = qptr[(size_t)(q0 + q) * DH + d];
    }

    // ---------------- Phase 1: S = Q @ K^T (pipelined) ----------------
    {
        const int qg = t >> 7;       // 0..1 : 8 q-rows (warp-uniform)
        const int kg = t & 127;      // 0..127: k-rows kg, kg+128

        unsigned long long acc[8][2];
#pragma unroll
        for (int i = 0; i < 8; i++) { acc[i][0] = 0ull; acc[i][1] = 0ull; }

        // issue chunk 0 (kt=0, dh0=0)
#pragma unroll
        for (int i2 = 0; i2 < 8; i2++) {
            const int idx = t + i2 * 256;
            const int row = idx >> 3, cc = (idx & 7) * 4;
            cpasync16(bufa[0] + (unsigned)(row * KSP + cc) * 4,
                      kptr + (size_t)row * DH + cc);
        }
        cp_commit();

        for (int c = 0; c < 16; c++) {
            if (c + 1 < 16) {
                const int kt1 = ((c + 1) >> 1) * KC, dh1 = ((c + 1) & 1) * 32;
                const unsigned ba = bufa[(c + 1) & 1];
#pragma unroll
                for (int i2 = 0; i2 < 8; i2++) {
                    const int idx = t + i2 * 256;
                    const int row = idx >> 3, cc = (idx & 7) * 4;
                    cpasync16(ba + (unsigned)(row * KSP + cc) * 4,
                              kptr + (size_t)(kt1 + row) * DH + dh1 + cc);
                }
                cp_commit();
                cp_wait1();
            } else {
                cp_wait0();
            }
            __syncthreads();

            const float* bcur = bufp[c & 1];
            const int dh0c = (c & 1) * 32;
#pragma unroll 2
            for (int dd4 = 0; dd4 < 32; dd4 += 4) {
                const ulonglong2 kv0 = *(const ulonglong2*)(bcur + kg * KSP + dd4);
                const ulonglong2 kv1 = *(const ulonglong2*)(bcur + (kg + 128) * KSP + dd4);
#pragma unroll
                for (int i = 0; i < 8; i++) {
                    const ulonglong2 qv =
                        *(const ulonglong2*)(Qs + (qg * 8 + i) * QSP + dh0c + dd4);
                    fma2(acc[i][0], qv.x, kv0.x); fma2(acc[i][0], qv.y, kv0.y);
                    fma2(acc[i][1], qv.x, kv1.x); fma2(acc[i][1], qv.y, kv1.y);
                }
            }
            if (c & 1) {   // both dd-halves of this kt done -> flush to S
                const int kt = (c >> 1) * KC;
#pragma unroll
                for (int i = 0; i < 8; i++) {
#pragma unroll
                    for (int j = 0; j < 2; j++) {
                        float lo, hi;
                        unpk(acc[i][j], lo, hi);
                        S[(qg * 8 + i) * SS + kt + kg + 128 * j] = lo + hi;
                        acc[i][j] = 0ull;
                    }
                }
            }
            __syncthreads();
        }
    }

    // prefetch phase-3 V chunk 0 (overlaps the whole softmax)
#pragma unroll
    for (int i2 = 0; i2 < 8; i2++) {
        const int idx = t + i2 * 256;
        const int row = idx >> 4, cc = (idx & 15) * 4;
        cpasync16(bufa[0] + (unsigned)(row * VSP + cc) * 4,
                  vptr + (size_t)row * DH + cc);
    }
    cp_commit();

    // ---------------- Phase 2: masked exp + sums (single pass) ----------------
    {
        const int w = t >> 5, lane = t & 31;
#pragma unroll
        for (int rr = 0; rr < 2; rr++) {
            const int r  = w * 2 + rr;
            const int qq = q0 + r;
            const int4* mrow4 = (const int4*)(mask + ((size_t)b * NL + qq) * NL);
            float4* srow4 = (float4*)(S + r * SS);

            float sum = 0.f;
            for (int i = lane; i < NL / 4; i += 32) {
                const float4 s = srow4[i];
                const int4   m = mrow4[i];
                float4 p;
                p.x = m.x ? 0.f : __expf(s.x);
                p.y = m.y ? 0.f : __expf(s.y);
                p.z = m.z ? 0.f : __expf(s.z);
                p.w = m.w ? 0.f : __expf(s.w);
                srow4[i] = p;
                sum += p.x + p.y + p.z + p.w;
            }
#pragma unroll
            for (int o = 16; o > 0; o >>= 1)
                sum += __shfl_xor_sync(0xffffffffu, sum, o);

            const float inv = 1.f / sum;
            if (lane == 0) invs[r] = inv;
            if (h == 0) {
                float4* arow4 = (float4*)(attn_out + ((size_t)b * NL + qq) * NL);
                for (int i = lane; i < NL / 4; i += 32) {
                    float4 p = srow4[i];
                    p.x *= inv; p.y *= inv; p.z *= inv; p.w *= inv;
                    arow4[i] = p;
                }
            }
        }
    }
    __syncthreads();

    // ---------------- Phase 3: ctx = P @ V (pipelined, ksplit x8) ----------------
    {
        const int ks = t >> 5;        // 0..7 : 16-row k-chunk within each 128-row tile
        const int qg = (t >> 4) & 1;  // 0..1 : 8 q-rows each
        const int dg = t & 15;        // 0..15: d columns dg*4 .. dg*4+3

        unsigned long long acc[8][2];
#pragma unroll
        for (int i = 0; i < 8; i++) { acc[i][0] = 0ull; acc[i][1] = 0ull; }

        for (int c = 0; c < 16; c++) {
            if (c + 1 < 16) {
                const unsigned ba = bufa[(c + 1) & 1];
#pragma unroll
                for (int i2 = 0; i2 < 8; i2++) {
                    const int idx = t + i2 * 256;
                    const int row = idx >> 4, cc = (idx & 15) * 4;
                    cpasync16(ba + (unsigned)(row * VSP + cc) * 4,
                              vptr + (size_t)((c + 1) * VC + row) * DH + cc);
                }
                cp_commit();
                cp_wait1();
            } else {
                cp_wait0();
            }
            __syncthreads();

            const float* bcur = bufp[c & 1];
#pragma unroll
            for (int kk4 = 0; kk4 < 16; kk4 += 4) {
                float4 pv[8];
#pragma unroll
                for (int i = 0; i < 8; i++)
                    pv[i] = *(const float4*)(S + (qg * 8 + i) * SS + c * VC + ks * 16 + kk4);
#pragma unroll
                for (int kk = 0; kk < 4; kk++) {
                    const ulonglong2 vv =
                        *(const ulonglong2*)(bcur + (ks * 16 + kk4 + kk) * VSP + dg * 4);
#pragma unroll
                    for (int i = 0; i < 8; i++) {
                        const float pf = (kk == 0) ? pv[i].x : (kk == 1) ? pv[i].y
                                       : (kk == 2) ? pv[i].z : pv[i].w;
                        const unsigned long long pd = pk2(pf);
                        fma2(acc[i][0], pd, vv.x);
                        fma2(acc[i][1], pd, vv.y);
                    }
                }
            }
            __syncthreads();
        }

        // reduction across the 8 k-split groups (red aliased onto buffers)
        float* red = bufp[0];
#pragma unroll
        for (int i = 0; i < 8; i++) {
            float* rb = red + ((ks * QT) + qg * 8 + i) * DH + dg * 4;
            *(unsigned long long*)(rb)     = acc[i][0];
            *(unsigned long long*)(rb + 2) = acc[i][1];
        }
        __syncthreads();

        float* ctx = g_ctx + (size_t)(b * NL + q0) * ND + h * DH;
        for (int idx = t; idx < QT * DH; idx += 256) {
            const int q = idx >> 6, d = idx & 63;
            float s = 0.f;
#pragma unroll
            for (int g = 0; g < 8; g++) s += red[(g * QT + q) * DH + d];
            ctx[(size_t)q * ND + d] = s * invs[q];
        }
    }
}

// ---------------------------------------------------------------------------
extern "C" void kernel_launch(void* const* d_in, const int* in_sizes, int n_in,
                              void* d_out, int out_size)
{
    const float* key   = (const float*)d_in[0];
    const float* value = (const float*)d_in[1];
    const float* query = (const float*)d_in[2];
    const int*   mask  = (const int*)d_in[3];
    const float* Wk = (const float*)d_in[4];
    const float* bk = (const float*)d_in[5];
    const float* Wv = (const float*)d_in[6];
    const float* bv = (const float*)d_in[7];
    const float* Wq = (const float*)d_in[8];
    const float* bq = (const float*)d_in[9];
    const float* Wo = (const float*)d_in[10];
    const float* bo = (const float*)d_in[11];

    float* out      = (float*)d_out;
    float* attn_out = out + (size_t)NB * NL * ND;

    float *gk, *gv, *gq, *gctx;
    cudaGetSymbolAddress((void**)&gk,   g_k);
    cudaGetSymbolAddress((void**)&gv,   g_v);
    cudaGetSymbolAddress((void**)&gq,   g_q);
    cudaGetSymbolAddress((void**)&gctx, g_ctx);

    static int attr_set = 0;
    if (!attr_set) {
        cudaFuncSetAttribute(attn_kernel,
                             cudaFuncAttributeMaxDynamicSharedMemorySize,
                             SMEM_FLOATS * (int)sizeof(float));
        attr_set = 1;
    }

    const dim3 gemm_grid(ND / 128, (NB * NL) / 128);  // 8 x 64
    sgemm_bias_kernel<<<gemm_grid, 256>>>(key,   Wk, bk, gk, 1.0f,   1);
    sgemm_bias_kernel<<<gemm_grid, 256>>>(value, Wv, bv, gv, 1.0f,   1);
    sgemm_bias_kernel<<<gemm_grid, 256>>>(query, Wq, bq, gq, 0.125f, 1);

    const dim3 attn_grid(NL / QT, NH, NB);            // 128 x 16 x 4
    attn_kernel<<<attn_grid, 256, SMEM_FLOATS * (int)sizeof(float)>>>(mask, attn_out);

    sgemm_bias_kernel<<<gemm_grid, 256>>>(gctx, Wo, bo, out, 1.0f, 0);
}